// round 2
// baseline (speedup 1.0000x reference)
#include <cuda_runtime.h>
#include <cuda_bf16.h>
#include <math.h>

#define TOK 4096            // 4 * 1024

// ---------------- scratch (no allocations allowed) ----------------
__device__ float g_qkv0[3][TOK * 192];   // Q,K,V for MHA0
__device__ float g_qkv1[3][TOK * 66];    // Q,K,V for MHA1
__device__ float g_c0[TOK * 192];
__device__ float g_c1[TOK * 66];

// ---------------- fused QKV GEMM: C_z = (A @ W_z + b_z) * scale_z -----------
struct Triple {
    const float* W[3];
    const float* B[3];
    float*       C[3];
    float        scale[3];
};

__global__ __launch_bounds__(256) void gemm64_3(
    Triple t, const float* __restrict__ A, int M, int N, int K)
{
    const float* __restrict__ W    = t.W[blockIdx.z];
    const float* __restrict__ bias = t.B[blockIdx.z];
    float* __restrict__ C          = t.C[blockIdx.z];
    const float scale              = t.scale[blockIdx.z];

    __shared__ float sAT[16][64];   // [k][row]
    __shared__ float sB[16][64];    // [k][col]

    const int tx = threadIdx.x, ty = threadIdx.y;
    const int tt = ty * 16 + tx;
    const int rBase = blockIdx.y * 64;
    const int cBase = blockIdx.x * 64;

    float acc[4][4];
#pragma unroll
    for (int i = 0; i < 4; i++)
#pragma unroll
        for (int j = 0; j < 4; j++) acc[i][j] = 0.f;

    for (int k0 = 0; k0 < K; k0 += 16) {
#pragma unroll
        for (int i = 0; i < 4; i++) {
            int idx = tt + i * 256;
            int kk = idx & 15;
            int r  = idx >> 4;
            int kg = k0 + kk;
            sAT[kk][r] = (kg < K) ? A[(size_t)(rBase + r) * K + kg] : 0.f;
        }
#pragma unroll
        for (int i = 0; i < 4; i++) {
            int idx = tt + i * 256;
            int c  = idx & 63;
            int kk = idx >> 6;
            int kg = k0 + kk;
            int cg = cBase + c;
            sB[kk][c] = (kg < K && cg < N) ? W[(size_t)kg * N + cg] : 0.f;
        }
        __syncthreads();
#pragma unroll
        for (int kk = 0; kk < 16; kk++) {
            float4 a = *(const float4*)&sAT[kk][ty * 4];
            float4 b = *(const float4*)&sB[kk][tx * 4];
            float av[4] = {a.x, a.y, a.z, a.w};
            float bv[4] = {b.x, b.y, b.z, b.w};
#pragma unroll
            for (int i = 0; i < 4; i++)
#pragma unroll
                for (int j = 0; j < 4; j++)
                    acc[i][j] = fmaf(av[i], bv[j], acc[i][j]);
        }
        __syncthreads();
    }

#pragma unroll
    for (int i = 0; i < 4; i++) {
        int r = rBase + ty * 4 + i;
#pragma unroll
        for (int j = 0; j < 4; j++) {
            int c = cBase + tx * 4 + j;
            if (c < N)
                C[(size_t)r * N + c] = (acc[i][j] + bias[c]) * scale;
        }
    }
}

// ---------------- flash attention v2 (TQ queries per thread) ----------------
// Scores already carry the log2(e)/sqrt(dph) factor (folded into Q projection),
// so softmax uses exp2f directly. Mask is a pre-computed additive bias.
template <int DPH, int TQ>
__global__ __launch_bounds__(128) void attn2(
    const float* __restrict__ Q, const float* __restrict__ K,
    const float* __restrict__ V, const int* __restrict__ mask,
    float* __restrict__ C, int n_heads, int qlen)
{
    const int dim = n_heads * DPH;
    const int b = blockIdx.x / n_heads;
    const int h = blockIdx.x % n_heads;
    const int qi0 = (blockIdx.y * 128 + threadIdx.x) * TQ;

    __shared__ float sK[128 * DPH];
    __shared__ float sV[128 * DPH];
    __shared__ float sBias[128];

    float q[TQ][DPH];
#pragma unroll
    for (int j = 0; j < TQ; j++) {
        const float* qp = Q + (size_t)(b * qlen + qi0 + j) * dim + h * DPH;
        if constexpr (DPH % 4 == 0) {
#pragma unroll
            for (int d = 0; d < DPH; d += 4) {
                float4 v4 = *(const float4*)(qp + d);
                q[j][d] = v4.x; q[j][d+1] = v4.y; q[j][d+2] = v4.z; q[j][d+3] = v4.w;
            }
        } else {
#pragma unroll
            for (int d = 0; d < DPH; d += 2) {
                float2 v2 = *(const float2*)(qp + d);
                q[j][d] = v2.x; q[j][d+1] = v2.y;
            }
        }
    }

    float m[TQ], l[TQ], acc[TQ][DPH];
#pragma unroll
    for (int j = 0; j < TQ; j++) {
        m[j] = -INFINITY; l[j] = 0.f;
#pragma unroll
        for (int d = 0; d < DPH; d++) acc[j][d] = 0.f;
    }

    for (int k0 = 0; k0 < qlen; k0 += 128) {
        {   // cooperative tile load: thread i loads key row k0+i
            int kk = threadIdx.x;
            const float* kp = K + (size_t)(b * qlen + k0 + kk) * dim + h * DPH;
            const float* vp = V + (size_t)(b * qlen + k0 + kk) * dim + h * DPH;
            if constexpr (DPH % 4 == 0) {
#pragma unroll
                for (int d = 0; d < DPH; d += 4) {
                    *(float4*)&sK[kk * DPH + d] = *(const float4*)(kp + d);
                    *(float4*)&sV[kk * DPH + d] = *(const float4*)(vp + d);
                }
            } else {
#pragma unroll
                for (int d = 0; d < DPH; d += 2) {
                    *(float2*)&sK[kk * DPH + d] = *(const float2*)(kp + d);
                    *(float2*)&sV[kk * DPH + d] = *(const float2*)(vp + d);
                }
            }
            sBias[kk] = mask[b * qlen + k0 + kk] ? 0.f : -1e30f;
        }
        __syncthreads();

#pragma unroll 2
        for (int k = 0; k < 128; k++) {
            float kr[DPH], vr[DPH];
            if constexpr (DPH % 4 == 0) {
#pragma unroll
                for (int d = 0; d < DPH; d += 4) {
                    float4 a = *(const float4*)&sK[k * DPH + d];
                    kr[d] = a.x; kr[d+1] = a.y; kr[d+2] = a.z; kr[d+3] = a.w;
                    float4 bv = *(const float4*)&sV[k * DPH + d];
                    vr[d] = bv.x; vr[d+1] = bv.y; vr[d+2] = bv.z; vr[d+3] = bv.w;
                }
            } else {
#pragma unroll
                for (int d = 0; d < DPH; d += 2) {
                    float2 a = *(const float2*)&sK[k * DPH + d];
                    kr[d] = a.x; kr[d+1] = a.y;
                    float2 bv = *(const float2*)&sV[k * DPH + d];
                    vr[d] = bv.x; vr[d+1] = bv.y;
                }
            }
            float bias = sBias[k];

            float dot[TQ];
#pragma unroll
            for (int j = 0; j < TQ; j++) {
                float d0 = 0.f, d1 = 0.f;   // split accumulators: 2 chains
#pragma unroll
                for (int d = 0; d < DPH; d += 2) {
                    d0 = fmaf(q[j][d],     kr[d],     d0);
                    d1 = fmaf(q[j][d + 1], kr[d + 1], d1);
                }
                dot[j] = d0 + d1 + bias;
            }

#pragma unroll
            for (int j = 0; j < TQ; j++) {
                if (dot[j] <= m[j]) {
                    float p = exp2f(dot[j] - m[j]);
                    l[j] += p;
#pragma unroll
                    for (int d = 0; d < DPH; d++)
                        acc[j][d] = fmaf(p, vr[d], acc[j][d]);
                } else {
                    float sc = exp2f(m[j] - dot[j]);
                    l[j] = fmaf(l[j], sc, 1.f);
#pragma unroll
                    for (int d = 0; d < DPH; d++)
                        acc[j][d] = fmaf(acc[j][d], sc, vr[d]);
                    m[j] = dot[j];
                }
            }
        }
        __syncthreads();
    }

#pragma unroll
    for (int j = 0; j < TQ; j++) {
        const float inv = 1.f / l[j];
        float* cp = C + (size_t)(b * qlen + qi0 + j) * dim + h * DPH;
        if constexpr (DPH % 4 == 0) {
#pragma unroll
            for (int d = 0; d < DPH; d += 4) {
                float4 o4 = make_float4(acc[j][d] * inv, acc[j][d+1] * inv,
                                        acc[j][d+2] * inv, acc[j][d+3] * inv);
                *(float4*)(cp + d) = o4;
            }
        } else {
#pragma unroll
            for (int d = 0; d < DPH; d += 2) {
                float2 o2 = make_float2(acc[j][d] * inv, acc[j][d+1] * inv);
                *(float2*)(cp + d) = o2;
            }
        }
    }
}

// ---------------- launch ----------------------------------------------------
extern "C" void kernel_launch(void* const* d_in, const int* in_sizes, int n_in,
                              void* d_out, int out_size)
{
    const float* x     = (const float*)d_in[0];
    const float* y     = (const float*)d_in[1];
    const int*   mask0 = (const int*)d_in[2];
    const int*   mask1 = (const int*)d_in[3];
    const float* q0_w = (const float*)d_in[4],  *q0_b = (const float*)d_in[5];
    const float* k0_w = (const float*)d_in[6],  *k0_b = (const float*)d_in[7];
    const float* v0_w = (const float*)d_in[8],  *v0_b = (const float*)d_in[9];
    const float* o0_w = (const float*)d_in[10], *o0_b = (const float*)d_in[11];
    const float* q1_w = (const float*)d_in[12], *q1_b = (const float*)d_in[13];
    const float* k1_w = (const float*)d_in[14], *k1_b = (const float*)d_in[15];
    const float* v1_w = (const float*)d_in[16], *v1_b = (const float*)d_in[17];
    const float* o1_w = (const float*)d_in[18], *o1_b = (const float*)d_in[19];

    float* out0 = (float*)d_out;
    float* out1 = out0 + (size_t)TOK * 192;

    float *qkv0, *qkv1, *c0, *c1;
    cudaGetSymbolAddress((void**)&qkv0, g_qkv0);
    cudaGetSymbolAddress((void**)&qkv1, g_qkv1);
    cudaGetSymbolAddress((void**)&c0, g_c0);
    cudaGetSymbolAddress((void**)&c1, g_c1);

    const float LOG2E = 1.4426950408889634f;
    const float s0 = LOG2E / sqrtf(12.0f);   // folded: 1/sqrt(dph) * log2(e)
    const float s1 = LOG2E / sqrtf(6.0f);

    dim3 blk(16, 16);

    // MHA0: fused QKV projection  (grid z = q/k/v)
    Triple t0;
    t0.W[0] = q0_w; t0.W[1] = k0_w; t0.W[2] = v0_w;
    t0.B[0] = q0_b; t0.B[1] = k0_b; t0.B[2] = v0_b;
    t0.C[0] = qkv0; t0.C[1] = qkv0 + (size_t)TOK * 192; t0.C[2] = qkv0 + (size_t)2 * TOK * 192;
    t0.scale[0] = s0; t0.scale[1] = 1.f; t0.scale[2] = 1.f;
    gemm64_3<<<dim3(3, 64, 3), blk>>>(t0, x, TOK, 192, 192);

    Triple t1;
    t1.W[0] = q1_w; t1.W[1] = k1_w; t1.W[2] = v1_w;
    t1.B[0] = q1_b; t1.B[1] = k1_b; t1.B[2] = v1_b;
    t1.C[0] = qkv1; t1.C[1] = qkv1 + (size_t)TOK * 66; t1.C[2] = qkv1 + (size_t)2 * TOK * 66;
    t1.scale[0] = s1; t1.scale[1] = 1.f; t1.scale[2] = 1.f;
    gemm64_3<<<dim3(2, 64, 3), blk>>>(t1, y, TOK, 66, 66);

    // attention (TQ = 2 queries per thread)
    attn2<12, 2><<<dim3(4 * 16, 4), 128>>>(
        t0.C[0], t0.C[1], t0.C[2], mask0, c0, 16, 1024);
    attn2<6, 2><<<dim3(4 * 11, 4), 128>>>(
        t1.C[0], t1.C[1], t1.C[2], mask1, c1, 11, 1024);

    // output projections (single-matrix via Triple with z extent 1)
    Triple to0;
    to0.W[0] = o0_w; to0.B[0] = o0_b; to0.C[0] = out0; to0.scale[0] = 1.f;
    to0.W[1] = to0.W[2] = o0_w; to0.B[1] = to0.B[2] = o0_b;
    to0.C[1] = to0.C[2] = out0; to0.scale[1] = to0.scale[2] = 1.f;
    gemm64_3<<<dim3(3, 64, 1), blk>>>(to0, c0, TOK, 192, 192);

    Triple to1;
    to1.W[0] = o1_w; to1.B[0] = o1_b; to1.C[0] = out1; to1.scale[0] = 1.f;
    to1.W[1] = to1.W[2] = o1_w; to1.B[1] = to1.B[2] = o1_b;
    to1.C[1] = to1.C[2] = out1; to1.scale[1] = to1.scale[2] = 1.f;
    gemm64_3<<<dim3(2, 64, 1), blk>>>(to1, c1, TOK, 66, 66);
}